// round 16
// baseline (speedup 1.0000x reference)
#include <cuda_runtime.h>
#include <cuda_bf16.h>

// Problem constants (LinearDiffusion_2860448219950)
#define NN   8192
#define HH   4
#define EE   131072
#define DD   64
#define WW   96                 // ELL width (max degree ~58 for Poisson(32) over 8192 rows)
#define TBL  (1 << 19)
#define TBLM (TBL - 1)

// ---------------- device scratch (no allocations allowed) ----------------
__device__ unsigned long long g_tbl[TBL];       // packed hash: hi32=key+1, lo32=prio
__device__ int          g_slot[2 * EE];
__device__ int          g_deg[NN];
__device__ float        g_rowsum[NN * HH];
__device__ int          g_cols[NN * WW];
__device__ float4       g_evals[NN * WW];       // unnormalized e-quads (fp32)
__device__ __nv_bfloat16 g_xb[3][NN * DD];      // bf16 x buffers, ROW-MAJOR (N,64): xh + ping-pong

__device__ __forceinline__ unsigned int hash_key(unsigned int key) {
    return (key * 2654435761u) >> 13;
}

__device__ __forceinline__ int ht_insert(unsigned int key, unsigned int prio) {
    unsigned long long desired = ((unsigned long long)(key + 1u) << 32) | prio;
    unsigned int s = hash_key(key) & TBLM;
    while (true) {
        unsigned long long cur = g_tbl[s];
        if (cur == 0ULL) {
            unsigned long long old = atomicCAS(&g_tbl[s], 0ULL, desired);
            if (old == 0ULL) return (int)s;
            cur = old;
        }
        if ((unsigned int)(cur >> 32) == key + 1u) {
            while ((unsigned int)cur < prio) {
                unsigned long long old = atomicCAS(&g_tbl[s], cur, desired);
                if (old == cur) break;
                cur = old;
            }
            return (int)s;
        }
        s = (s + 1) & TBLM;
    }
}

// ---------------- 1: hash insert ----------------
__global__ void k_insert(const int* __restrict__ src, const int* __restrict__ dst) {
    int t = blockIdx.x * blockDim.x + threadIdx.x;
    if (t >= 2 * EE) return;
    int pass = (t >= EE);
    int k = t - (pass ? EE : 0);
    int a = src[k], b = dst[k];
    int i = pass ? b : a;
    int j = pass ? a : b;
    unsigned int key  = ((unsigned int)i << 13) | (unsigned int)j;
    unsigned int prio = (((unsigned int)pass << 17)) + (unsigned int)k + 1u;
    g_slot[t] = ht_insert(key, prio);
}

// ---------------- 2: winners -> ELL + degree + rowsum ----------------
__global__ void k_winner(const int* __restrict__ src, const int* __restrict__ dst,
                         const float* __restrict__ e) {
    int t = blockIdx.x * blockDim.x + threadIdx.x;
    if (t >= 2 * EE) return;
    int pass = (t >= EE);
    int k = t - (pass ? EE : 0);
    unsigned int prio = (((unsigned int)pass << 17)) + (unsigned int)k + 1u;
    unsigned long long entry = g_tbl[g_slot[t]];
    if ((unsigned int)entry != prio) return;
    int a = src[k], b = dst[k];
    int i = pass ? b : a;
    int j = pass ? a : b;
    float4 ev;
    ev.x = e[0 * EE + k]; ev.y = e[1 * EE + k];
    ev.z = e[2 * EE + k]; ev.w = e[3 * EE + k];
    int pos = atomicAdd(&g_deg[i], 1);
    if (pos < WW) {
        g_cols[i * WW + pos]  = j;
        g_evals[i * WW + pos] = ev;
    }
    atomicAdd(&g_rowsum[i * HH + 0], ev.x);
    atomicAdd(&g_rowsum[i * HH + 1], ev.y);
    atomicAdd(&g_rowsum[i * HH + 2], ev.z);
    atomicAdd(&g_rowsum[i * HH + 3], ev.w);
}

// ---------------- 2b: transpose h (H,N,16) fp32 -> (N,64) bf16 row-major ----------------
__global__ void k_transpose(const float4* __restrict__ h4, uint2* __restrict__ xh) {
    int t = blockIdx.x * blockDim.x + threadIdx.x;   // NN*16 threads
    int row = t >> 4, c = t & 15, head = c >> 2, q = c & 3;
    float4 x = __ldg(&h4[(head << 15) + (row << 2) + q]);
    __nv_bfloat162 b0 = __floats2bfloat162_rn(x.x, x.y);
    __nv_bfloat162 b1 = __floats2bfloat162_rn(x.z, x.w);
    uint2 w;
    w.x = *reinterpret_cast<unsigned int*>(&b0);
    w.y = *reinterpret_cast<unsigned int*>(&b1);
    xh[(row << 4) + c] = w;
}

// ---------------- 3: SpMM  xi = (A_unnorm @ xin)/rowsum ; res (+)= xi*invf ----------------
// 32 threads/row, lane = 16*sub + c; sub in {0,1} takes one contiguous half of
// the row's edges; c = head*4 + q. x buffers bf16 row-major (N,64): one 128B
// line per gathered row. Column indices prefetched once into registers and
// distributed per-edge via shfl -> x-gather addresses never wait on an L2 load.
// res keeps the fixed (H,N,16)-flat fp32 layout of the harness.
template <bool FIRST>
__global__ void k_spmm(const uint2* __restrict__ xinb, uint2* __restrict__ xoutb,
                       float4* __restrict__ res4, const float4* __restrict__ h4,
                       float invf) {
    int tid = threadIdx.x;
    int row = blockIdx.x * 8 + (tid >> 5);
    int lane = tid & 31;
    int sub = lane >> 4;
    int c = lane & 15;
    int head = c >> 2;
    int q = c & 3;
    int deg = g_deg[row];
    int half = (deg + 1) >> 1;                 // warp-uniform loop bound
    int rbeg = sub * half;
    int cnt = (sub ? deg - half : half);       // this sub's edge count
    const float* vals = (const float*)g_evals;
    int base = row * WW;
    // prefetch up to 32 cols for this sub (2 coalesced lane-parallel loads)
    int jr0 = (c < cnt)      ? g_cols[base + rbeg + c]      : 0;
    int jr1 = (16 + c < cnt) ? g_cols[base + rbeg + 16 + c] : 0;
    float4 acc = make_float4(0.f, 0.f, 0.f, 0.f);
#pragma unroll 1
    for (int u0 = 0; u0 < half; u0 += 8) {
        float v[8]; uint2 w[8];
#pragma unroll
        for (int t = 0; t < 8; t++) {
            int u = u0 + t;
            int jj;
            if (u < 32) {
                jj = __shfl_sync(0xFFFFFFFFu, (u & 16) ? jr1 : jr0, (sub << 4) + (u & 15));
            } else {                            // deg > 64 fallback (astronomically rare)
                jj = (u < cnt) ? g_cols[base + rbeg + u] : 0;
            }
            bool ok = (u < cnt);
            v[t] = ok ? vals[(base + rbeg + u) * 4 + head] : 0.f;
            w[t] = ok ? __ldg(&xinb[(jj << 4) + c]) : make_uint2(0u, 0u);
        }
#pragma unroll
        for (int t = 0; t < 8; t++) {
            float2 lo = __bfloat1622float2(*reinterpret_cast<__nv_bfloat162*>(&w[t].x));
            float2 hi = __bfloat1622float2(*reinterpret_cast<__nv_bfloat162*>(&w[t].y));
            acc.x += v[t] * lo.x; acc.y += v[t] * lo.y;
            acc.z += v[t] * hi.x; acc.w += v[t] * hi.y;
        }
    }
    acc.x += __shfl_xor_sync(0xFFFFFFFFu, acc.x, 16);
    acc.y += __shfl_xor_sync(0xFFFFFFFFu, acc.y, 16);
    acc.z += __shfl_xor_sync(0xFFFFFFFFu, acc.z, 16);
    acc.w += __shfl_xor_sync(0xFFFFFFFFu, acc.w, 16);
    if (sub == 0) {
        float rinv = 1.0f / g_rowsum[row * HH + head];
        float4 xi = make_float4(acc.x * rinv, acc.y * rinv, acc.z * rinv, acc.w * rinv);
        __nv_bfloat162 b0 = __floats2bfloat162_rn(xi.x, xi.y);
        __nv_bfloat162 b1 = __floats2bfloat162_rn(xi.z, xi.w);
        uint2 w;
        w.x = *reinterpret_cast<unsigned int*>(&b0);
        w.y = *reinterpret_cast<unsigned int*>(&b1);
        xoutb[(row << 4) + c] = w;
        int o = (head << 15) + (row << 2) + q;  // res in fixed (H,N,16) layout
        if (FIRST) {
            float4 hv = __ldg(&h4[o]);          // exact fp32 h base
            res4[o] = make_float4(hv.x + xi.x, hv.y + xi.y, hv.z + xi.z, hv.w + xi.w);
        } else {
            float4 rv = res4[o];
            res4[o] = make_float4(rv.x + xi.x * invf, rv.y + xi.y * invf,
                                  rv.z + xi.z * invf, rv.w + xi.w * invf);
        }
    }
}

// ---------------- launch ----------------
extern "C" void kernel_launch(void* const* d_in, const int* in_sizes, int n_in,
                              void* d_out, int out_size) {
    const float* h   = (const float*)d_in[0];
    const float* e   = (const float*)d_in[1];
    const int*   src = (const int*)d_in[2];
    const int*   dst = (const int*)d_in[3];
    float4* out4 = (float4*)d_out;

    // zero scratch via memset nodes (graph-capturable, engine-rate)
    void* p;
    cudaGetSymbolAddress(&p, g_tbl);
    cudaMemsetAsync(p, 0, TBL * sizeof(unsigned long long));
    cudaGetSymbolAddress(&p, g_deg);
    cudaMemsetAsync(p, 0, NN * sizeof(int));
    cudaGetSymbolAddress(&p, g_rowsum);
    cudaMemsetAsync(p, 0, NN * HH * sizeof(float));

    k_insert<<<(2 * EE + 255) / 256, 256>>>(src, dst);
    k_winner<<<(2 * EE + 255) / 256, 256>>>(src, dst, e);

    __nv_bfloat16* xh;
    cudaGetSymbolAddress((void**)&xh, g_xb);
    __nv_bfloat16* xa = xh + NN * DD;
    __nv_bfloat16* xb = xa + NN * DD;

    // h -> bf16 row-major staging (runs concurrently with insert/winner-independent path)
    k_transpose<<<(NN * 16) / 256, 256>>>((const float4*)h, (uint2*)xh);

    const float invf[6] = {1.0f, 0.5f, 1.0f / 6.0f, 1.0f / 24.0f, 1.0f / 120.0f, 1.0f / 720.0f};
    // Hop 1: gather bf16 xh -> bf16 xa, fused res = h + x1 (h base read in fp32)
    k_spmm<true><<<NN / 8, 256>>>((const uint2*)xh, (uint2*)xa, out4,
                                  (const float4*)h, invf[0]);
    const __nv_bfloat16* cur = xa;
    __nv_bfloat16* bufs[2] = {xa, xb};    // it=1 -> xb, it=2 -> xa, alternating vs cur
    for (int it = 1; it < 6; it++) {
        __nv_bfloat16* nxt = bufs[it & 1];
        k_spmm<false><<<NN / 8, 256>>>((const uint2*)cur, (uint2*)nxt, out4,
                                       (const float4*)h, invf[it]);
        cur = nxt;
    }
}